// round 13
// baseline (speedup 1.0000x reference)
#include <cuda_runtime.h>

// Problem constants
#define TT    1024   // seq len
#define BB    1024   // batch
#define HH    64     // encoder hidden
#define NB    7      // batch elements per CTA
#define CTAS  147    // 147*7 = 1029 >= 1024

// ---------------------------------------------------------------------------
// helpers
// ---------------------------------------------------------------------------
__device__ __forceinline__ void ffma2(unsigned long long &d,
                                      unsigned long long a,
                                      unsigned long long b) {
    asm("fma.rn.f32x2 %0, %1, %2, %0;" : "+l"(d) : "l"(a), "l"(b));
}
__device__ __forceinline__ unsigned long long packf2(float lo, float hi) {
    unsigned long long r;
    asm("mov.b64 %0, {%1,%2};" : "=l"(r) : "f"(lo), "f"(hi));
    return r;
}
__device__ __forceinline__ float ex2f(float x) {
    float r; asm("ex2.approx.f32 %0, %1;" : "=f"(r) : "f"(x)); return r;
}
__device__ __forceinline__ float rcpf(float x) {
    float r; asm("rcp.approx.f32 %0, %1;" : "=f"(r) : "f"(x)); return r;
}

#define L2E      1.4426950408889634f
#define TWO_L2E  2.8853900817779268f

__device__ __forceinline__ float tanhx(float x) {      // rel err ~1e-7
    return fmaf(-2.0f, rcpf(1.0f + ex2f(TWO_L2E * x)), 1.0f);
}

// ---------------------------------------------------------------------------
// Fused encoder+decoder. 147 CTAs x 256 threads (2 warps/SMSP).
// == R4 (best: 1189us) + two-wave software pipeline (R12, with the x-timing
//    bug fixed: ALL accumulator inits consume this step's x BEFORE the
//    prefetch overwrites xv) ==
//
// Two independent 128-thread subgroups per CTA own batches {0..3} / {4..6},
// each with its own named barrier so their phases drift on each SMSP.
//
// Per-thread math (identical to R4): j = (tid&127)>>1, half = tid&1
//   half0 -> gate rows (i,f) = (j, j+64); half1 -> (g,o) = (j+128, j+192)
// 2 gate rows of Whh in regs (64 packed f32x2); activation arg scale folded
// into weights/bias.
//
// Step structure:
//   acc init A+B (this step's x)  ->  prefetch next x
//   matvec A (b0,b1) -> activations A (MUFU chains launch)
//   matvec B (b2[,b3])            <- covers MUFU latency of A
//   shuffle/c/tanh/store A        <- A's acts are mature by now
//   activations B -> shuffle/c/tanh/store B
//   per-subgroup barrier
// Same instruction counts as R4; only issue order changes. Both halves
// update c; only half0 computes tanh(c) and stores h. hs double-buffered.
// Decoder (hidden=1) fused at the end after a full __syncthreads.
// ---------------------------------------------------------------------------
__global__ void __launch_bounds__(256, 1) fused_kernel(
    const float* __restrict__ x,      // [T, B, 1]
    const float* __restrict__ Wih,    // [256, 1]
    const float* __restrict__ Whh,    // [256, 64]
    const float* __restrict__ bih,    // [256]
    const float* __restrict__ bhh,    // [256]
    const float* __restrict__ Wih_d,  // [4, 64]
    const float* __restrict__ Whh_d,  // [4, 1]
    const float* __restrict__ bih_d,  // [4]
    const float* __restrict__ bhh_d,  // [4]
    float* __restrict__ out)          // [T, B, 1]
{
    const int tid  = threadIdx.x;
    const int sub  = tid >> 7;            // 0 or 1
    const int j    = (tid & 127) >> 1;    // 0..63
    const int half = tid & 1;
    const int r0   = half * 128 + j;      // i (half0) / g (half1)
    const int r1   = r0 + 64;             // f (half0) / o (half1)
    const int b0   = blockIdx.x * NB;

    const int nb     = sub ? 3 : 4;
    const int b_base = sub ? 4 : 0;

    __shared__ __align__(16) float hs[2][NB][HH];  // double-buffered hidden

    // activation parametrization (r0: sigmoid/tanh, r1: sigmoid)
    const float s0 = half ? TWO_L2E : -L2E;
    const float s1 = -L2E;
    const float A0 = half ? -2.0f : 1.0f;
    const float B0 = half ?  1.0f : 0.0f;

    // weights for my two gate rows, pre-scaled, packed over k
    unsigned long long w0[32], w1[32];
    {
        const float2* p0 = (const float2*)(Whh + r0 * HH);
        const float2* p1 = (const float2*)(Whh + r1 * HH);
        #pragma unroll
        for (int i = 0; i < 32; i++) {
            float2 v0 = p0[i], v1 = p1[i];
            w0[i] = packf2(v0.x * s0, v0.y * s0);
            w1[i] = packf2(v1.x * s1, v1.y * s1);
        }
    }
    const float be0  = s0 * (bih[r0] + bhh[r0]);
    const float be1  = s1 * (bih[r1] + bhh[r1]);
    const float wih0 = s0 * Wih[r0];
    const float wih1 = s1 * Wih[r1];

    // per-batch x offsets (clamped duplicates deterministic)
    int off[4];
    #pragma unroll
    for (int bi = 0; bi < 4; bi++) {
        int gb = b0 + b_base + bi; if (gb > BB - 1) gb = BB - 1;
        off[bi] = gb;
    }
    float xv[4];
    #pragma unroll
    for (int bi = 0; bi < 4; bi++) if (bi < nb) xv[bi] = __ldg(x + off[bi]);

    // init h = 0 (buffer 0)
    for (int i = tid; i < NB * HH; i += 256) ((float*)hs[0])[i] = 0.0f;
    float cc[4] = {0.0f, 0.0f, 0.0f, 0.0f};
    __syncthreads();

    const float* xt = x + BB;   // next step's x row

    for (int t = 0; t < TT; t++) {
        const float* __restrict__ hr = hs[t & 1][0];
        float* __restrict__       hw = hs[(t + 1) & 1][0];

        // ---- accumulator init for BOTH waves (this step's x), THEN prefetch
        unsigned long long a0[2], a1[2];     // wave A: batches 0,1
        #pragma unroll
        for (int bi = 0; bi < 2; bi++) {
            a0[bi] = packf2(fmaf(wih0, xv[bi], be0), 0.0f);
            a1[bi] = packf2(fmaf(wih1, xv[bi], be1), 0.0f);
        }
        unsigned long long c0a[2], c1a[2];   // wave B: batches 2[,3]
        #pragma unroll
        for (int bi = 2; bi < 4; bi++) if (bi < nb) {
            c0a[bi - 2] = packf2(fmaf(wih0, xv[bi], be0), 0.0f);
            c1a[bi - 2] = packf2(fmaf(wih1, xv[bi], be1), 0.0f);
        }

        // prefetch next x (safe now: all inits already consumed xv)
        if (t + 1 < TT) {
            #pragma unroll
            for (int bi = 0; bi < 4; bi++)
                if (bi < nb) xv[bi] = __ldg(xt + off[bi]);
        }

        // ---- matvec A ----
        #pragma unroll
        for (int kk = 0; kk < 16; kk++) {
            #pragma unroll
            for (int bi = 0; bi < 2; bi++) {
                ulonglong2 h4 =
                    ((const ulonglong2*)(hr + (b_base + bi) * HH))[kk];
                ffma2(a0[bi], w0[2 * kk],     h4.x);
                ffma2(a0[bi], w0[2 * kk + 1], h4.y);
                ffma2(a1[bi], w1[2 * kk],     h4.x);
                ffma2(a1[bi], w1[2 * kk + 1], h4.y);
            }
        }

        // activations A: launch MUFU chains; they mature under matvec B
        float act0A[2], act1A[2];
        #pragma unroll
        for (int bi = 0; bi < 2; bi++) {
            float l0, h0, l1, h1;
            asm("mov.b64 {%0,%1}, %2;" : "=f"(l0), "=f"(h0) : "l"(a0[bi]));
            asm("mov.b64 {%0,%1}, %2;" : "=f"(l1), "=f"(h1) : "l"(a1[bi]));
            act0A[bi] = fmaf(A0, rcpf(1.0f + ex2f(l0 + h0)), B0);
            act1A[bi] = rcpf(1.0f + ex2f(l1 + h1));
        }

        // ---- matvec B (covers MUFU latency of wave A) ----
        #pragma unroll
        for (int kk = 0; kk < 16; kk++) {
            #pragma unroll
            for (int bi = 2; bi < 4; bi++) if (bi < nb) {
                ulonglong2 h4 =
                    ((const ulonglong2*)(hr + (b_base + bi) * HH))[kk];
                ffma2(c0a[bi - 2], w0[2 * kk],     h4.x);
                ffma2(c0a[bi - 2], w0[2 * kk + 1], h4.y);
                ffma2(c1a[bi - 2], w1[2 * kk],     h4.x);
                ffma2(c1a[bi - 2], w1[2 * kk + 1], h4.y);
            }
        }

        // finish wave A: butterfly + c/h update (acts are mature)
        #pragma unroll
        for (int bi = 0; bi < 2; bi++) {
            float p0 = __shfl_xor_sync(0xffffffffu, act0A[bi], 1);
            float p1 = __shfl_xor_sync(0xffffffffu, act1A[bi], 1);
            float ai = half ? p0        : act0A[bi];
            float af = half ? p1        : act1A[bi];
            float ag = half ? act0A[bi] : p0;
            float ao = half ? act1A[bi] : p1;
            cc[bi] = fmaf(af, cc[bi], ai * ag);
            if (!half) {
                float hn = ao * tanhx(cc[bi]);
                hw[(b_base + bi) * HH + j] = hn;
            }
        }

        // activations B
        float act0B[2], act1B[2];
        #pragma unroll
        for (int bi = 2; bi < 4; bi++) if (bi < nb) {
            float l0, h0, l1, h1;
            asm("mov.b64 {%0,%1}, %2;" : "=f"(l0), "=f"(h0) : "l"(c0a[bi - 2]));
            asm("mov.b64 {%0,%1}, %2;" : "=f"(l1), "=f"(h1) : "l"(c1a[bi - 2]));
            act0B[bi - 2] = fmaf(A0, rcpf(1.0f + ex2f(l0 + h0)), B0);
            act1B[bi - 2] = rcpf(1.0f + ex2f(l1 + h1));
        }

        // finish wave B
        #pragma unroll
        for (int bi = 2; bi < 4; bi++) if (bi < nb) {
            float p0 = __shfl_xor_sync(0xffffffffu, act0B[bi - 2], 1);
            float p1 = __shfl_xor_sync(0xffffffffu, act1B[bi - 2], 1);
            float ai = half ? p0            : act0B[bi - 2];
            float af = half ? p1            : act1B[bi - 2];
            float ag = half ? act0B[bi - 2] : p0;
            float ao = half ? act1B[bi - 2] : p1;
            cc[bi] = fmaf(af, cc[bi], ai * ag);
            if (!half) {
                float hn = ao * tanhx(cc[bi]);
                hw[(b_base + bi) * HH + j] = hn;
            }
        }

        // per-subgroup barrier: hs slices are subgroup-private
        asm volatile("bar.sync %0, %1;" :: "r"(sub + 1), "r"(128) : "memory");
        xt += BB;
    }
    // final h in hs[0] (t=1023 wrote buffer (1024)&1 = 0)
    __syncthreads();   // decoder reads all batches

    // ------------------- fused decoder (7 threads per CTA) -------------------
    if (tid < NB) {
        const int gb = b0 + tid;
        if (gb < BB) {
            const float* he = hs[0][tid];
            float z[4], wd[4];
            #pragma unroll
            for (int g = 0; g < 4; g++) {
                float acc = bih_d[g] + bhh_d[g];
                const float* wr = Wih_d + g * HH;
                #pragma unroll 8
                for (int k = 0; k < HH; k++) acc = fmaf(wr[k], he[k], acc);
                const float s = (g == 2) ? TWO_L2E : -L2E;
                z[g]  = s * acc;
                wd[g] = s * Whh_d[g];
            }
            float h = 0.0f, c = 0.0f;
            float* op = out + gb;
            for (int t = 0; t < TT; t++) {
                float gi = fmaf(wd[0], h, z[0]);
                float gf = fmaf(wd[1], h, z[1]);
                float gg = fmaf(wd[2], h, z[2]);
                float go = fmaf(wd[3], h, z[3]);
                float ai = rcpf(1.0f + ex2f(gi));
                float af = rcpf(1.0f + ex2f(gf));
                float ag = fmaf(-2.0f, rcpf(1.0f + ex2f(gg)), 1.0f);
                float ao = rcpf(1.0f + ex2f(go));
                c = fmaf(af, c, ai * ag);
                h = ao * tanhx(c);
                *op = h;
                op += BB;
            }
        }
    }
}

// ---------------------------------------------------------------------------
// launch
// ---------------------------------------------------------------------------
extern "C" void kernel_launch(void* const* d_in, const int* in_sizes, int n_in,
                              void* d_out, int out_size) {
    const float* x     = (const float*)d_in[0];
    const float* Wih_e = (const float*)d_in[1];
    const float* Whh_e = (const float*)d_in[2];
    const float* bih_e = (const float*)d_in[3];
    const float* bhh_e = (const float*)d_in[4];
    const float* Wih_d = (const float*)d_in[5];
    const float* Whh_d = (const float*)d_in[6];
    const float* bih_d = (const float*)d_in[7];
    const float* bhh_d = (const float*)d_in[8];
    float* out = (float*)d_out;

    fused_kernel<<<CTAS, 256>>>(x, Wih_e, Whh_e, bih_e, bhh_e,
                                Wih_d, Whh_d, bih_d, bhh_d, out);
}

// round 14
// speedup vs baseline: 2.0284x; 2.0284x over previous
#include <cuda_runtime.h>

// Problem constants
#define TT    1024   // seq len
#define BB    1024   // batch
#define HH    64     // encoder hidden
#define NBT   8      // batches per CTA
#define CTAS  128    // 128*8 = 1024 exactly

// ---------------------------------------------------------------------------
// helpers
// ---------------------------------------------------------------------------
__device__ __forceinline__ float ex2f(float x) {
    float r; asm("ex2.approx.f32 %0, %1;" : "=f"(r) : "f"(x)); return r;
}
__device__ __forceinline__ float rcpf(float x) {
    float r; asm("rcp.approx.f32 %0, %1;" : "=f"(r) : "f"(x)); return r;
}
__device__ __forceinline__ unsigned tf32_bits(float f) {
    unsigned r; asm("cvt.rna.tf32.f32 %0, %1;" : "=r"(r) : "f"(f)); return r;
}
__device__ __forceinline__ void mma_tf32(float& c0, float& c1, float& c2, float& c3,
                                         unsigned a0, unsigned a1, unsigned a2, unsigned a3,
                                         unsigned b0, unsigned b1) {
    asm("mma.sync.aligned.m16n8k8.row.col.f32.tf32.tf32.f32 "
        "{%0,%1,%2,%3},{%4,%5,%6,%7},{%8,%9},{%0,%1,%2,%3};"
        : "+f"(c0), "+f"(c1), "+f"(c2), "+f"(c3)
        : "r"(a0), "r"(a1), "r"(a2), "r"(a3), "r"(b0), "r"(b1));
}
__device__ __forceinline__ float sel4(float v0, float v1, float v2, float v3, int k) {
    float a = (k & 1) ? v1 : v0;
    float b = (k & 1) ? v3 : v2;
    return (k & 2) ? b : a;
}

#define L2E      1.4426950408889634f
#define TWO_L2E  2.8853900817779268f

__device__ __forceinline__ float tanhx(float x) {      // rel err ~1e-7
    return fmaf(-2.0f, rcpf(1.0f + ex2f(TWO_L2E * x)), 1.0f);
}

// ---------------------------------------------------------------------------
// Fused encoder+decoder via mma.sync tf32 tensor cores.
// 128 CTAs x 256 threads; CTA owns 8 batch chains (perfectly balanced).
//
// Gate matrix rows are PERMUTED so warp w's 32-row A-tile holds all 4 gates
// of hidden indices j in [8w, 8w+8):  row'(32w + rr) -> physical row
// g*64 + (8w + rr>>2) with g = rr&3.  Consequence: each thread's C rows are
// a single gate g = (lane>>2)&3, and the i/f/g/o combine for any (j, batch)
// is WARP-LOCAL (3 shfl_xor: lanes l^4, l^8, l^12 hold the other gates).
//
// Per step per warp: 8 LDS.64 (B = h fragments, tf32 bits, slot-permuted,
// stride-68 rows), 16 mma.sync m16n8k8 (2 m-tiles x 8 k-tiles, split into
// two 4-deep accumulate chains + join), activations (per-lane sigmoid/tanh
// constants), 6 shfl_xor gather, 2 owned c/h items per lane, 2 STS of
// tf32(h) into the other h buffer.  ONE __syncthreads per step (h double-
// buffered).  Gate-arg scale folded into weights+bias before tf32 rounding.
// x is prefetched one step ahead into a double-buffered SMEM stage.
// Exact fp32 h is saved to hfin at the last step for the decoder.
//
// h slot permutation (so b0/b1 of a k-tile are adjacent -> LDS.64):
//   slot(k) = (k>>3)*8 + (k&3)*2 + ((k>>2)&1)
// B frag (k = 8kt + (lane&3) and +4, n = lane>>2) reads words
//   n*68 + 8kt + 2*(lane&3), +1.
// Decoder (hidden=1) fused at the end: 8 threads per CTA.
// ---------------------------------------------------------------------------
__global__ void __launch_bounds__(256, 1) fused_kernel(
    const float* __restrict__ x,      // [T, B, 1]
    const float* __restrict__ Wih,    // [256, 1]
    const float* __restrict__ Whh,    // [256, 64]
    const float* __restrict__ bih,    // [256]
    const float* __restrict__ bhh,    // [256]
    const float* __restrict__ Wih_d,  // [4, 64]
    const float* __restrict__ Whh_d,  // [4, 1]
    const float* __restrict__ bih_d,  // [4]
    const float* __restrict__ bhh_d,  // [4]
    float* __restrict__ out)          // [T, B, 1]
{
    const int tid  = threadIdx.x;
    const int w    = tid >> 5;
    const int lane = tid & 31;
    const int gi   = (lane >> 2) & 3;     // my C-rows' gate (0..3)
    const int J    = lane >> 4;           // 0/1
    const int n0   = 2 * (lane & 3);      // my C-fragment batch pair
    const int b0   = blockIdx.x * NBT;

    __shared__ __align__(16) unsigned hsm[2][NBT][68];  // tf32 h, double-buffered
    __shared__ __align__(16) float xs[2][NBT];          // x stage, double-buffered
    __shared__ __align__(16) float hfin[NBT][HH];       // exact final h (decoder)

    // activation parametrization for my gate (gi==2 is tanh)
    const float s  = (gi == 2) ? TWO_L2E : -L2E;
    const float Am = (gi == 2) ? -2.0f : 1.0f;
    const float Bm = (gi == 2) ?  1.0f : 0.0f;

    // ---- A weights: 2 m-tiles x 8 k-tiles x 4 regs, scale folded, tf32 ----
    unsigned wa[2][8][4];
    #pragma unroll
    for (int T = 0; T < 2; T++) {
        const int jA = 8 * w + J + 4 * T;        // jj for a0/a2 rows
        const int r0 = gi * HH + jA;             // physical row (a0/a2)
        const int r1 = r0 + 2;                   // a1/a3 rows (jj+2)
        #pragma unroll
        for (int kt = 0; kt < 8; kt++) {
            const int k0 = 8 * kt + (lane & 3);
            wa[T][kt][0] = tf32_bits(s * Whh[r0 * HH + k0]);
            wa[T][kt][1] = tf32_bits(s * Whh[r1 * HH + k0]);
            wa[T][kt][2] = tf32_bits(s * Whh[r0 * HH + k0 + 4]);
            wa[T][kt][3] = tf32_bits(s * Whh[r1 * HH + k0 + 4]);
        }
    }
    // bias + input-coef per m (jj = J + 2m), scale folded
    float bs[4], ws[4];
    #pragma unroll
    for (int m = 0; m < 4; m++) {
        const int row = gi * HH + 8 * w + J + 2 * m;
        bs[m] = s * (bih[row] + bhh[row]);
        ws[m] = s * Wih[row];
    }

    // my owned c/h items: (jj_own, n0) and (jj_own, n0+1)
    const int jj_own = 2 * gi + J;
    const int jmine  = 8 * w + jj_own;
    const int slot   = 8 * w + (jj_own & 3) * 2 + ((jj_own >> 2) & 1);

    // init: h(bits)=0 in buffer 0, x stage for t=0
    for (int i = tid; i < NBT * 68; i += 256) ((unsigned*)hsm[0])[i] = 0u;
    if (tid < NBT) xs[0][tid] = x[b0 + tid];
    float cc[2] = {0.0f, 0.0f};
    __syncthreads();

    for (int t = 0; t < TT; t++) {
        const int p = t & 1;

        // x for my batch pair (LDS.64) + early prefetch of next step's x
        float2 xx = *(const float2*)&xs[p][n0];
        float xpre = 0.0f;
        if ((tid < NBT) && (t + 1 < TT)) xpre = __ldg(&x[(t + 1) * BB + b0 + tid]);

        // B fragments (h of this step): 8 x LDS.64
        const unsigned* hb = &hsm[p][lane >> 2][0];
        uint2 bb[8];
        #pragma unroll
        for (int kt = 0; kt < 8; kt++)
            bb[kt] = *(const uint2*)&hb[8 * kt + 2 * (lane & 3)];

        // accumulators: accA (kt 0-3) init with bias+x, accB (kt 4-7) init 0
        float accA[2][4], accB[2][4];
        #pragma unroll
        for (int T = 0; T < 2; T++)
            #pragma unroll
            for (int q = 0; q < 4; q++) {
                const int m = 2 * T + (q >> 1);
                accA[T][q] = fmaf(ws[m], (q & 1) ? xx.y : xx.x, bs[m]);
                accB[T][q] = 0.0f;
            }

        // 16 mma.sync: two 4-deep chains per accumulator group
        #pragma unroll
        for (int kt = 0; kt < 4; kt++) {
            mma_tf32(accA[0][0], accA[0][1], accA[0][2], accA[0][3],
                     wa[0][kt][0], wa[0][kt][1], wa[0][kt][2], wa[0][kt][3],
                     bb[kt].x, bb[kt].y);
            mma_tf32(accA[1][0], accA[1][1], accA[1][2], accA[1][3],
                     wa[1][kt][0], wa[1][kt][1], wa[1][kt][2], wa[1][kt][3],
                     bb[kt].x, bb[kt].y);
        }
        #pragma unroll
        for (int kt = 4; kt < 8; kt++) {
            mma_tf32(accB[0][0], accB[0][1], accB[0][2], accB[0][3],
                     wa[0][kt][0], wa[0][kt][1], wa[0][kt][2], wa[0][kt][3],
                     bb[kt].x, bb[kt].y);
            mma_tf32(accB[1][0], accB[1][1], accB[1][2], accB[1][3],
                     wa[1][kt][0], wa[1][kt][1], wa[1][kt][2], wa[1][kt][3],
                     bb[kt].x, bb[kt].y);
        }

        // activations: act[m][ns]  (m = jj slot, ns = batch-in-pair)
        float act[4][2];
        #pragma unroll
        for (int T = 0; T < 2; T++)
            #pragma unroll
            for (int q = 0; q < 4; q++) {
                const int m  = 2 * T + (q >> 1);
                const int ns = q & 1;
                float v = accA[T][q] + accB[T][q];
                act[m][ns] = fmaf(Am, rcpf(1.0f + ex2f(v)), Bm);
            }

        // warp-local 4-gate gather + c/h update for my 2 items
        #pragma unroll
        for (int ns = 0; ns < 2; ns++) {
            float s1 = sel4(act[0][ns], act[1][ns], act[2][ns], act[3][ns], gi ^ 1);
            float s2 = sel4(act[0][ns], act[1][ns], act[2][ns], act[3][ns], gi ^ 2);
            float s3 = sel4(act[0][ns], act[1][ns], act[2][ns], act[3][ns], gi ^ 3);
            float r0 = sel4(act[0][ns], act[1][ns], act[2][ns], act[3][ns], gi);
            float r1 = __shfl_xor_sync(0xffffffffu, s1, 4);
            float r2 = __shfl_xor_sync(0xffffffffu, s2, 8);
            float r3 = __shfl_xor_sync(0xffffffffu, s3, 12);
            // gate value of rD is gi^D  ->  gate G sits at D = gi^G
            float vi = sel4(r0, r1, r2, r3, gi);
            float vf = sel4(r0, r1, r2, r3, gi ^ 1);
            float vg = sel4(r0, r1, r2, r3, gi ^ 2);
            float vo = sel4(r0, r1, r2, r3, gi ^ 3);
            cc[ns] = fmaf(vf, cc[ns], vi * vg);
            float hn = vo * tanhx(cc[ns]);
            hsm[p ^ 1][n0 + ns][slot] = tf32_bits(hn);
            if (t == TT - 1) hfin[n0 + ns][jmine] = hn;
        }

        if ((tid < NBT) && (t + 1 < TT)) xs[p ^ 1][tid] = xpre;
        __syncthreads();
    }

    // ------------------- fused decoder (8 threads per CTA) -------------------
    if (tid < NBT) {
        const float* he = hfin[tid];
        float z[4], wd[4];
        #pragma unroll
        for (int g = 0; g < 4; g++) {
            float acc = bih_d[g] + bhh_d[g];
            const float* wr = Wih_d + g * HH;
            #pragma unroll 8
            for (int k = 0; k < HH; k++) acc = fmaf(wr[k], he[k], acc);
            const float sd = (g == 2) ? TWO_L2E : -L2E;
            z[g]  = sd * acc;
            wd[g] = sd * Whh_d[g];
        }
        float h = 0.0f, c = 0.0f;
        float* op = out + b0 + tid;
        for (int t = 0; t < TT; t++) {
            float gi_ = fmaf(wd[0], h, z[0]);
            float gf  = fmaf(wd[1], h, z[1]);
            float gg  = fmaf(wd[2], h, z[2]);
            float go  = fmaf(wd[3], h, z[3]);
            float ai = rcpf(1.0f + ex2f(gi_));
            float af = rcpf(1.0f + ex2f(gf));
            float ag = fmaf(-2.0f, rcpf(1.0f + ex2f(gg)), 1.0f);
            float ao = rcpf(1.0f + ex2f(go));
            c = fmaf(af, c, ai * ag);
            h = ao * tanhx(c);
            *op = h;
            op += BB;
        }
    }
}

// ---------------------------------------------------------------------------
// launch
// ---------------------------------------------------------------------------
extern "C" void kernel_launch(void* const* d_in, const int* in_sizes, int n_in,
                              void* d_out, int out_size) {
    const float* x     = (const float*)d_in[0];
    const float* Wih_e = (const float*)d_in[1];
    const float* Whh_e = (const float*)d_in[2];
    const float* bih_e = (const float*)d_in[3];
    const float* bhh_e = (const float*)d_in[4];
    const float* Wih_d = (const float*)d_in[5];
    const float* Whh_d = (const float*)d_in[6];
    const float* bih_d = (const float*)d_in[7];
    const float* bhh_d = (const float*)d_in[8];
    float* out = (float*)d_out;

    fused_kernel<<<CTAS, 256>>>(x, Wih_e, Whh_e, bih_e, bhh_e,
                                Wih_d, Whh_d, bih_d, bhh_d, out);
}

// round 15
// speedup vs baseline: 2.7108x; 1.3364x over previous
#include <cuda_runtime.h>

// Problem constants
#define TT    1024   // seq len
#define BB    1024   // batch
#define HH    64     // encoder hidden
#define NBR   7      // real batches per CTA (clamped duplicates beyond 1023)
#define CTAS  148    // 148*7 = 1036 >= 1024; all SMs busy

// ---------------------------------------------------------------------------
// helpers
// ---------------------------------------------------------------------------
__device__ __forceinline__ float tanhapx(float x) {    // MUFU.TANH, 1 instr
    float r; asm("tanh.approx.f32 %0, %1;" : "=r"(*(unsigned*)&r) : "f"(x));
    return r;
}
__device__ __forceinline__ unsigned tf32_bits(float f) {
    unsigned r; asm("cvt.rna.tf32.f32 %0, %1;" : "=r"(r) : "f"(f)); return r;
}
__device__ __forceinline__ void mma_tf32(float& c0, float& c1, float& c2, float& c3,
                                         unsigned a0, unsigned a1, unsigned a2, unsigned a3,
                                         unsigned b0, unsigned b1) {
    asm("mma.sync.aligned.m16n8k8.row.col.f32.tf32.tf32.f32 "
        "{%0,%1,%2,%3},{%4,%5,%6,%7},{%8,%9},{%0,%1,%2,%3};"
        : "+f"(c0), "+f"(c1), "+f"(c2), "+f"(c3)
        : "r"(a0), "r"(a1), "r"(a2), "r"(a3), "r"(b0), "r"(b1));
}
__device__ __forceinline__ float sel4(float v0, float v1, float v2, float v3, int k) {
    float a = (k & 1) ? v1 : v0;
    float b = (k & 1) ? v3 : v2;
    return (k & 2) ? b : a;
}

// ---------------------------------------------------------------------------
// Fused encoder+decoder via mma.sync tf32 tensor cores (R14 winner) with:
//  (1) 148 CTAs x 7 batches (all SMs; batch >=1024 clamps to 1023 -- the
//      duplicated chains are bit-identical, so racing output writes agree),
//  (2) tanh.approx activations: sigmoid(v) = 0.5 + 0.5*tanh(v/2) with the
//      0.5 folded into weights/bias; tanh gate & tanh(c) direct. Halves the
//      MUFU instruction count and shortens every dependent activation chain,
//  (3) mma accumulators split 4 ways (depth-2 chains + join tree).
//
// Layout (unchanged from R14): warp w owns permuted 32-row A-tile = all 4
// gates of j in [8w, 8w+8); thread C-rows are one gate gi=(lane>>2)&3; the
// i/f/g/o combine is warp-local (3 shfl_xor + selects). One __syncthreads
// per step; h kept as tf32 bits in double-buffered SMEM (stride 68);
// exact fp32 h saved at t=1023 for the fused decoder (8 threads).
// ---------------------------------------------------------------------------
__global__ void __launch_bounds__(256, 1) fused_kernel(
    const float* __restrict__ x,      // [T, B, 1]
    const float* __restrict__ Wih,    // [256, 1]
    const float* __restrict__ Whh,    // [256, 64]
    const float* __restrict__ bih,    // [256]
    const float* __restrict__ bhh,    // [256]
    const float* __restrict__ Wih_d,  // [4, 64]
    const float* __restrict__ Whh_d,  // [4, 1]
    const float* __restrict__ bih_d,  // [4]
    const float* __restrict__ bhh_d,  // [4]
    float* __restrict__ out)          // [T, B, 1]
{
    const int tid  = threadIdx.x;
    const int w    = tid >> 5;
    const int lane = tid & 31;
    const int gi   = (lane >> 2) & 3;     // my C-rows' gate (0..3)
    const int J    = lane >> 4;           // 0/1
    const int n0   = 2 * (lane & 3);      // my C-fragment batch pair
    const int b0   = blockIdx.x * NBR;

    __shared__ __align__(16) unsigned hsm[2][8][68];  // tf32 h, double-buffered
    __shared__ __align__(16) float xs[2][8];          // x stage, double-buffered
    __shared__ __align__(16) float hfin[8][HH];       // exact final h (decoder)

    // activation parametrization for my gate:
    //   sigmoid rows: v' = v/2 (folded), act = 0.5*tanh(v') + 0.5
    //   tanh row (gi==2): v' = v,       act = tanh(v')
    const float s  = (gi == 2) ? 1.0f : 0.5f;
    const float Am = (gi == 2) ? 1.0f : 0.5f;
    const float Bm = (gi == 2) ? 0.0f : 0.5f;

    // ---- A weights: 2 m-tiles x 8 k-tiles x 4 regs, scale folded, tf32 ----
    unsigned wa[2][8][4];
    #pragma unroll
    for (int T = 0; T < 2; T++) {
        const int jA = 8 * w + J + 4 * T;        // jj for a0/a2 rows
        const int r0 = gi * HH + jA;             // physical row (a0/a2)
        const int r1 = r0 + 2;                   // a1/a3 rows (jj+2)
        #pragma unroll
        for (int kt = 0; kt < 8; kt++) {
            const int k0 = 8 * kt + (lane & 3);
            wa[T][kt][0] = tf32_bits(s * Whh[r0 * HH + k0]);
            wa[T][kt][1] = tf32_bits(s * Whh[r1 * HH + k0]);
            wa[T][kt][2] = tf32_bits(s * Whh[r0 * HH + k0 + 4]);
            wa[T][kt][3] = tf32_bits(s * Whh[r1 * HH + k0 + 4]);
        }
    }
    // bias + input-coef per m (jj = J + 2m), scale folded
    float bs[4], ws[4];
    #pragma unroll
    for (int m = 0; m < 4; m++) {
        const int row = gi * HH + 8 * w + J + 2 * m;
        bs[m] = s * (bih[row] + bhh[row]);
        ws[m] = s * Wih[row];
    }

    // my owned c/h items: (jj_own, n0) and (jj_own, n0+1)
    const int jj_own = 2 * gi + J;
    const int jmine  = 8 * w + jj_own;
    const int slot   = 8 * w + (jj_own & 3) * 2 + ((jj_own >> 2) & 1);

    // init: h(bits)=0 in buffer 0, x stage for t=0 (batch clamped)
    for (int i = tid; i < 8 * 68; i += 256) ((unsigned*)hsm[0])[i] = 0u;
    if (tid < 8) {
        int gb = b0 + tid; if (gb > BB - 1) gb = BB - 1;
        xs[0][tid] = x[gb];
    }
    float cc[2] = {0.0f, 0.0f};
    __syncthreads();

    for (int t = 0; t < TT; t++) {
        const int p = t & 1;

        // x for my batch pair (LDS.64) + early prefetch of next step's x
        float2 xx = *(const float2*)&xs[p][n0];
        float xpre = 0.0f;
        if ((tid < 8) && (t + 1 < TT)) {
            int gb = b0 + tid; if (gb > BB - 1) gb = BB - 1;
            xpre = __ldg(&x[(t + 1) * BB + gb]);
        }

        // B fragments (h of this step): 8 x LDS.64
        const unsigned* hb = &hsm[p][lane >> 2][0];
        uint2 bb[8];
        #pragma unroll
        for (int kt = 0; kt < 8; kt++)
            bb[kt] = *(const uint2*)&hb[8 * kt + 2 * (lane & 3)];

        // 4-way split accumulators: A(kt0-1, bias+x), B(kt2-3), C(kt4-5), D(kt6-7)
        float aA[2][4], aB[2][4], aC[2][4], aD[2][4];
        #pragma unroll
        for (int T = 0; T < 2; T++)
            #pragma unroll
            for (int q = 0; q < 4; q++) {
                const int m = 2 * T + (q >> 1);
                aA[T][q] = fmaf(ws[m], (q & 1) ? xx.y : xx.x, bs[m]);
                aB[T][q] = 0.0f; aC[T][q] = 0.0f; aD[T][q] = 0.0f;
            }

        // 16 mma.sync as 8 depth-2 chains
        #pragma unroll
        for (int T = 0; T < 2; T++) {
            mma_tf32(aA[T][0], aA[T][1], aA[T][2], aA[T][3],
                     wa[T][0][0], wa[T][0][1], wa[T][0][2], wa[T][0][3], bb[0].x, bb[0].y);
            mma_tf32(aB[T][0], aB[T][1], aB[T][2], aB[T][3],
                     wa[T][2][0], wa[T][2][1], wa[T][2][2], wa[T][2][3], bb[2].x, bb[2].y);
            mma_tf32(aC[T][0], aC[T][1], aC[T][2], aC[T][3],
                     wa[T][4][0], wa[T][4][1], wa[T][4][2], wa[T][4][3], bb[4].x, bb[4].y);
            mma_tf32(aD[T][0], aD[T][1], aD[T][2], aD[T][3],
                     wa[T][6][0], wa[T][6][1], wa[T][6][2], wa[T][6][3], bb[6].x, bb[6].y);
            mma_tf32(aA[T][0], aA[T][1], aA[T][2], aA[T][3],
                     wa[T][1][0], wa[T][1][1], wa[T][1][2], wa[T][1][3], bb[1].x, bb[1].y);
            mma_tf32(aB[T][0], aB[T][1], aB[T][2], aB[T][3],
                     wa[T][3][0], wa[T][3][1], wa[T][3][2], wa[T][3][3], bb[3].x, bb[3].y);
            mma_tf32(aC[T][0], aC[T][1], aC[T][2], aC[T][3],
                     wa[T][5][0], wa[T][5][1], wa[T][5][2], wa[T][5][3], bb[5].x, bb[5].y);
            mma_tf32(aD[T][0], aD[T][1], aD[T][2], aD[T][3],
                     wa[T][7][0], wa[T][7][1], wa[T][7][2], wa[T][7][3], bb[7].x, bb[7].y);
        }

        // activations: act[m][ns] via single tanh.approx each
        float act[4][2];
        #pragma unroll
        for (int T = 0; T < 2; T++)
            #pragma unroll
            for (int q = 0; q < 4; q++) {
                const int m  = 2 * T + (q >> 1);
                const int ns = q & 1;
                float v = (aA[T][q] + aB[T][q]) + (aC[T][q] + aD[T][q]);
                act[m][ns] = fmaf(Am, tanhapx(v), Bm);
            }

        // warp-local 4-gate gather + c/h update for my 2 items
        #pragma unroll
        for (int ns = 0; ns < 2; ns++) {
            float s1 = sel4(act[0][ns], act[1][ns], act[2][ns], act[3][ns], gi ^ 1);
            float s2 = sel4(act[0][ns], act[1][ns], act[2][ns], act[3][ns], gi ^ 2);
            float s3 = sel4(act[0][ns], act[1][ns], act[2][ns], act[3][ns], gi ^ 3);
            float r0 = sel4(act[0][ns], act[1][ns], act[2][ns], act[3][ns], gi);
            float r1 = __shfl_xor_sync(0xffffffffu, s1, 4);
            float r2 = __shfl_xor_sync(0xffffffffu, s2, 8);
            float r3 = __shfl_xor_sync(0xffffffffu, s3, 12);
            // gate value of rD is gi^D  ->  gate G sits at D = gi^G
            float vi = sel4(r0, r1, r2, r3, gi);
            float vf = sel4(r0, r1, r2, r3, gi ^ 1);
            float vg = sel4(r0, r1, r2, r3, gi ^ 2);
            float vo = sel4(r0, r1, r2, r3, gi ^ 3);
            cc[ns] = fmaf(vf, cc[ns], vi * vg);
            float hn = vo * tanhapx(cc[ns]);
            hsm[p ^ 1][n0 + ns][slot] = tf32_bits(hn);
            if (t == TT - 1) hfin[n0 + ns][jmine] = hn;
        }

        if ((tid < 8) && (t + 1 < TT)) xs[p ^ 1][tid] = xpre;
        __syncthreads();
    }

    // ------------------- fused decoder (8 threads per CTA) -------------------
    if (tid < 8) {
        const float* he = hfin[tid];
        int gb = b0 + tid; if (gb > BB - 1) gb = BB - 1;  // clamped dup: same data
        float z[4], wd[4];
        #pragma unroll
        for (int g = 0; g < 4; g++) {
            float acc = bih_d[g] + bhh_d[g];
            const float* wr = Wih_d + g * HH;
            #pragma unroll 8
            for (int k = 0; k < HH; k++) acc = fmaf(wr[k], he[k], acc);
            const float sd = (g == 2) ? 1.0f : 0.5f;
            z[g]  = sd * acc;
            wd[g] = sd * Whh_d[g];
        }
        float h = 0.0f, c = 0.0f;
        float* op = out + gb;
        for (int t = 0; t < TT; t++) {
            float ai = fmaf(0.5f, tanhapx(fmaf(wd[0], h, z[0])), 0.5f);
            float af = fmaf(0.5f, tanhapx(fmaf(wd[1], h, z[1])), 0.5f);
            float ag = tanhapx(fmaf(wd[2], h, z[2]));
            float ao = fmaf(0.5f, tanhapx(fmaf(wd[3], h, z[3])), 0.5f);
            c = fmaf(af, c, ai * ag);
            h = ao * tanhapx(c);
            *op = h;           // clamped duplicates race with identical values
            op += BB;
        }
    }
}

// ---------------------------------------------------------------------------
// launch
// ---------------------------------------------------------------------------
extern "C" void kernel_launch(void* const* d_in, const int* in_sizes, int n_in,
                              void* d_out, int out_size) {
    const float* x     = (const float*)d_in[0];
    const float* Wih_e = (const float*)d_in[1];
    const float* Whh_e = (const float*)d_in[2];
    const float* bih_e = (const float*)d_in[3];
    const float* bhh_e = (const float*)d_in[4];
    const float* Wih_d = (const float*)d_in[5];
    const float* Whh_d = (const float*)d_in[6];
    const float* bih_d = (const float*)d_in[7];
    const float* bhh_d = (const float*)d_in[8];
    float* out = (float*)d_out;

    fused_kernel<<<CTAS, 256>>>(x, Wih_e, Whh_e, bih_e, bhh_e,
                                Wih_d, Whh_d, bih_d, bhh_d, out);
}